// round 8
// baseline (speedup 1.0000x reference)
#include <cuda_runtime.h>
#include <cuda_bf16.h>
#include <cuda_fp16.h>
#include <cstdint>
#include <cstddef>

// ---------------------------------------------------------------------------
// SageLayer pipeline v6: single-product fp16 HMMA GEMM (K=384).
//   out[b] = normalize(leaky( X @ A^T + c ))[nodes_idx]
//   X[u] = [ emb[uid[u]] | mean_k emb[adj[u,k]] | mean_k emb[dis[u,k]] ]
//   A, c folded (exact fp32 algebra). X, A rounded to fp16 -> rel_err ~2e-4,
//   5x under the 1e-3 threshold (error model validated in rounds 3-5).
// ---------------------------------------------------------------------------

#define U_NODES 16384
#define K_NEIGH 32
#define D_IN    128
#define D_OUT   384
#define B_OUT   32768

// ---- device scratch ----
__device__ __align__(16) float g_Padj[128 * 128];
__device__ __align__(16) float g_Pdis[128 * 128];
__device__ __align__(16) float g_qadj[128];
__device__ __align__(16) float g_qdis[128];
__device__ __align__(16) float g_c[384];
__device__ __align__(16) __half g_X[(size_t)U_NODES * 384];
__device__ __align__(16) __half g_B[384 * 384];            // folded A[n][k]
__device__ __align__(16) float g_Y[(size_t)U_NODES * 384];

// ---- helpers ----
__device__ __forceinline__ uint32_t smem_u32(const void* p) {
    uint32_t a;
    asm("{ .reg .u64 t; cvta.to.shared.u64 t, %1; cvt.u32.u64 %0, t; }"
        : "=r"(a) : "l"(p));
    return a;
}
__device__ __forceinline__ void cp_async16(uint32_t dst, const void* src) {
    asm volatile("cp.async.cg.shared.global [%0], [%1], 16;"
                 :: "r"(dst), "l"(src) : "memory");
}
__device__ __forceinline__ void cp_commit() {
    asm volatile("cp.async.commit_group;" ::: "memory");
}
template <int N>
__device__ __forceinline__ void cp_wait() {
    asm volatile("cp.async.wait_group %0;" :: "n"(N) : "memory");
}
__device__ __forceinline__ void ldsm_x4(uint32_t& r0, uint32_t& r1,
                                        uint32_t& r2, uint32_t& r3, uint32_t a) {
    asm volatile("ldmatrix.sync.aligned.m8n8.x4.shared.b16 {%0,%1,%2,%3}, [%4];"
                 : "=r"(r0), "=r"(r1), "=r"(r2), "=r"(r3) : "r"(a));
}
__device__ __forceinline__ void mma16816(float& c0, float& c1, float& c2, float& c3,
                                         uint32_t a0, uint32_t a1, uint32_t a2, uint32_t a3,
                                         uint32_t b0, uint32_t b1) {
    asm volatile(
        "mma.sync.aligned.m16n8k16.row.col.f32.f16.f16.f32 "
        "{%0,%1,%2,%3}, {%4,%5,%6,%7}, {%8,%9}, {%0,%1,%2,%3};"
        : "+f"(c0), "+f"(c1), "+f"(c2), "+f"(c3)
        : "r"(a0), "r"(a1), "r"(a2), "r"(a3), "r"(b0), "r"(b1));
}

// ---------------------------------------------------------------------------
// fold1: P = W @ Wa (128x128), q = W @ ba   for adj/dis
// ---------------------------------------------------------------------------
__global__ void fold1_kernel(const float* __restrict__ W_adj,
                             const float* __restrict__ Wa_adj,
                             const float* __restrict__ ba_adj,
                             const float* __restrict__ W_dis,
                             const float* __restrict__ Wa_dis,
                             const float* __restrict__ ba_dis) {
    const int g = blockIdx.x;
    const int which = blockIdx.y;
    const int d = threadIdx.x;

    const float* W  = which ? W_dis  : W_adj;
    const float* Wa = which ? Wa_dis : Wa_adj;
    const float* ba = which ? ba_dis : ba_adj;
    float* P = which ? g_Pdis : g_Padj;
    float* q = which ? g_qdis : g_qadj;

    float acc = 0.f;
#pragma unroll 8
    for (int e = 0; e < 128; e++)
        acc += W[g * 128 + e] * Wa[e * 128 + d];
    P[g * 128 + d] = acc;

    __shared__ float red[128];
    red[d] = W[g * 128 + d] * ba[d];
    __syncthreads();
#pragma unroll
    for (int s = 64; s > 0; s >>= 1) {
        if (d < s) red[d] += red[d + s];
        __syncthreads();
    }
    if (d == 0) q[g] = red[0];
}

// ---------------------------------------------------------------------------
// fold2: folded A[n][k] -> fp16 (row-major N x K), and c[n]
// ---------------------------------------------------------------------------
__global__ void fold2_kernel(const float* __restrict__ WC,
                             const float* __restrict__ W_self,
                             const float* __restrict__ bWC,
                             const float* __restrict__ bias) {
    const int n = blockIdx.x;
    const int k = threadIdx.x;

    float acc = 0.f;
    if (k < 128) {
#pragma unroll 8
        for (int e = 0; e < 128; e++)
            acc += WC[n * 384 + e] * W_self[e * 128 + k];
    } else if (k < 256) {
        const int kk = k - 128;
#pragma unroll 8
        for (int g = 0; g < 128; g++)
            acc += WC[n * 384 + 128 + g] * g_Padj[g * 128 + kk];
    } else {
        const int kk = k - 256;
#pragma unroll 8
        for (int g = 0; g < 128; g++)
            acc += WC[n * 384 + 256 + g] * g_Pdis[g * 128 + kk];
    }
    g_B[n * 384 + k] = __float2half_rn(acc);

    float cp = 0.f;
    if (k >= 128 && k < 256) cp = WC[n * 384 + k] * g_qadj[k - 128];
    else if (k >= 256)       cp = WC[n * 384 + k] * g_qdis[k - 256];

    __shared__ float red[384];
    red[k] = cp;
    __syncthreads();
    if (k < 128) red[k] = red[k] + red[k + 128] + red[k + 256];
    __syncthreads();
#pragma unroll
    for (int s = 64; s > 0; s >>= 1) {
        if (k < s) red[k] += red[k + s];
        __syncthreads();
    }
    if (k == 0) g_c[n] = red[0] + bWC[n] + bias[n];
}

// ---------------------------------------------------------------------------
// gather_mean: X[u] = [self | mean_adj | mean_dis] -> fp16
// 16384 CTAs x 128 threads: max outstanding-load parallelism (DRAM-bound).
// ---------------------------------------------------------------------------
__global__ void gather_mean_kernel(const float* __restrict__ emb,
                                   const int* __restrict__ uid,
                                   const int* __restrict__ adj,
                                   const int* __restrict__ dis) {
    const int u = blockIdx.x;
    const int t = threadIdx.x;

    __shared__ int sa[K_NEIGH];
    __shared__ int sd[K_NEIGH];
    __shared__ int sself;
    if (t < 32)       sa[t]      = adj[u * K_NEIGH + t];
    else if (t < 64)  sd[t - 32] = dis[u * K_NEIGH + (t - 32)];
    else if (t == 64) sself      = uid[u];
    __syncthreads();

    float acc_a = 0.f, acc_d = 0.f;
#pragma unroll
    for (int k = 0; k < K_NEIGH; k++) {
        acc_a += emb[(size_t)sa[k] * D_IN + t];
        acc_d += emb[(size_t)sd[k] * D_IN + t];
    }
    const float selfv = emb[(size_t)sself * D_IN + t];

    const size_t r = (size_t)u * 384;
    g_X[r + t]       = __float2half_rn(selfv);
    g_X[r + 128 + t] = __float2half_rn(acc_a * (1.0f / 32.0f));
    g_X[r + 256 + t] = __float2half_rn(acc_d * (1.0f / 32.0f));
}

// ---------------------------------------------------------------------------
// GEMM: Y = leaky( X[16384,384] @ A^T + c ) via single-product fp16 mma.sync
// K = 384, k-chunk 64, 6 iters. CTA 128x128, 8 warps (4m x 2n), warp 32x64.
// 3-stage cp.async pipeline, ONE __syncthreads per iter.
// smem rows padded to 144 B (stride 36 words -> conflict-free ldmatrix).
// ---------------------------------------------------------------------------
#define KCH      64
#define ROWB     144                    // bytes per smem row (64 fp16 + pad)
#define STG_OP   (128 * ROWB)           // 18432 B per operand per stage
#define STG_B    (2 * STG_OP)           // 36864 B per stage (A+B)
#define NSTG     3
#define GSM_TOT  (NSTG * STG_B)         // 110592 B

__global__ __launch_bounds__(256, 2) void gemm_hmma_kernel() {
    extern __shared__ char gsm[];
    const uint32_t base = smem_u32(gsm);

    const int t = threadIdx.x;
    const int lane = t & 31;
    const int wid = t >> 5;
    const int wm = wid & 3;          // 4 m-warps x 32 rows
    const int wn = wid >> 2;         // 2 n-warps x 64 cols
    const int n0 = blockIdx.x * 128;
    const int m0 = blockIdx.y * 128;

    // ldmatrix per-lane address offsets (bytes)
    const uint32_t a_lm = (uint32_t)((lane & 15) * ROWB + (lane >> 4) * 16);
    const uint32_t b_lm = (uint32_t)(((lane & 7) + ((lane >> 4) << 3)) * ROWB
                                     + (((lane >> 3) & 1) << 4));

    float acc[2][8][4];
#pragma unroll
    for (int i = 0; i < 2; i++)
#pragma unroll
        for (int j = 0; j < 8; j++)
#pragma unroll
            for (int q = 0; q < 4; q++) acc[i][j][q] = 0.f;

    // load k-chunk for iter it (0..5) into stage s
    auto load_iter = [&](int it, int s) {
        const int kc = it * KCH;
        const uint32_t sb = base + (uint32_t)(s * STG_B);
#pragma unroll
        for (int j = 0; j < 4; j++) {
            const int q = t + j * 256;          // 0..1023
            const int r = q >> 3;               // row 0..127
            const int ch = q & 7;               // 16B chunk (8 per 128B row)
            cp_async16(sb + (uint32_t)(r * ROWB + ch * 16),
                       g_X + (size_t)(m0 + r) * 384 + kc + ch * 8);
            cp_async16(sb + (uint32_t)(STG_OP + r * ROWB + ch * 16),
                       g_B + (size_t)(n0 + r) * 384 + kc + ch * 8);
        }
        cp_commit();
    };

    load_iter(0, 0);
    load_iter(1, 1);

    for (int it = 0; it < 6; it++) {
        if (it == 5) cp_wait<0>(); else cp_wait<1>();
        __syncthreads();

        const int s = it % NSTG;
        const uint32_t a_tile = base + (uint32_t)(s * STG_B + wm * 32 * ROWB) + a_lm;
        const uint32_t b_tile = base + (uint32_t)(s * STG_B + STG_OP + wn * 64 * ROWB) + b_lm;

#pragma unroll
        for (int ks = 0; ks < 4; ks++) {
            uint32_t af[2][4];
            uint32_t bf_[4][4];
#pragma unroll
            for (int mi = 0; mi < 2; mi++)
                ldsm_x4(af[mi][0], af[mi][1], af[mi][2], af[mi][3],
                        a_tile + (uint32_t)(mi * 16 * ROWB + ks * 32));
#pragma unroll
            for (int bj = 0; bj < 4; bj++)
                ldsm_x4(bf_[bj][0], bf_[bj][1], bf_[bj][2], bf_[bj][3],
                        b_tile + (uint32_t)(bj * 16 * ROWB + ks * 32));
#pragma unroll
            for (int mi = 0; mi < 2; mi++)
#pragma unroll
                for (int nj = 0; nj < 8; nj++)
                    mma16816(acc[mi][nj][0], acc[mi][nj][1],
                             acc[mi][nj][2], acc[mi][nj][3],
                             af[mi][0], af[mi][1], af[mi][2], af[mi][3],
                             bf_[nj >> 1][(nj & 1) * 2],
                             bf_[nj >> 1][(nj & 1) * 2 + 1]);
        }

        if (it + 2 < 6) load_iter(it + 2, (it + 2) % NSTG);
    }

    // ---- epilogue: += c, leaky relu, store to g_Y ----
    float cv[8][2];
#pragma unroll
    for (int nj = 0; nj < 8; nj++) {
        const int col = n0 + wn * 64 + nj * 8 + (lane & 3) * 2;
        cv[nj][0] = g_c[col];
        cv[nj][1] = g_c[col + 1];
    }
#pragma unroll
    for (int mi = 0; mi < 2; mi++) {
        const int row = m0 + wm * 32 + mi * 16 + (lane >> 2);
#pragma unroll
        for (int nj = 0; nj < 8; nj++) {
            const int col = n0 + wn * 64 + nj * 8 + (lane & 3) * 2;
            float y0 = acc[mi][nj][0] + cv[nj][0];
            float y1 = acc[mi][nj][1] + cv[nj][1];
            float y2 = acc[mi][nj][2] + cv[nj][0];
            float y3 = acc[mi][nj][3] + cv[nj][1];
            y0 = (y0 > 0.f) ? y0 : 0.2f * y0;
            y1 = (y1 > 0.f) ? y1 : 0.2f * y1;
            y2 = (y2 > 0.f) ? y2 : 0.2f * y2;
            y3 = (y3 > 0.f) ? y3 : 0.2f * y3;
            *(float2*)&g_Y[(size_t)row * 384 + col]       = make_float2(y0, y1);
            *(float2*)&g_Y[(size_t)(row + 8) * 384 + col] = make_float2(y2, y3);
        }
    }
}

// ---------------------------------------------------------------------------
// norm_gather: out[b] = normalize(Y[nodes_idx[b]])
// ---------------------------------------------------------------------------
__global__ void norm_gather_kernel(const int* __restrict__ nodes_idx,
                                   float* __restrict__ out) {
    const int w = threadIdx.x >> 5;
    const int l = threadIdx.x & 31;
    const int b = blockIdx.x * 8 + w;
    const int u = nodes_idx[b];

    const float4* yr = (const float4*)(g_Y + (size_t)u * 384);
    float4 v0 = yr[l];
    float4 v1 = yr[l + 32];
    float4 v2 = yr[l + 64];

    float s = v0.x * v0.x + v0.y * v0.y + v0.z * v0.z + v0.w * v0.w
            + v1.x * v1.x + v1.y * v1.y + v1.z * v1.z + v1.w * v1.w
            + v2.x * v2.x + v2.y * v2.y + v2.z * v2.z + v2.w * v2.w;
#pragma unroll
    for (int off = 16; off > 0; off >>= 1)
        s += __shfl_xor_sync(0xffffffffu, s, off);

    const float inv = 1.0f / fmaxf(sqrtf(s), 1e-12f);

    float4* o = (float4*)(out + (size_t)b * 384);
    v0.x *= inv; v0.y *= inv; v0.z *= inv; v0.w *= inv;
    v1.x *= inv; v1.y *= inv; v1.z *= inv; v1.w *= inv;
    v2.x *= inv; v2.y *= inv; v2.z *= inv; v2.w *= inv;
    o[l]      = v0;
    o[l + 32] = v1;
    o[l + 64] = v2;
}

// ---------------------------------------------------------------------------
extern "C" void kernel_launch(void* const* d_in, const int* in_sizes, int n_in,
                              void* d_out, int out_size) {
    const float* emb    = (const float*)d_in[0];
    const float* Wa_adj = (const float*)d_in[1];
    const float* ba_adj = (const float*)d_in[2];
    const float* Wa_dis = (const float*)d_in[3];
    const float* ba_dis = (const float*)d_in[4];
    const float* W_self = (const float*)d_in[5];
    const float* W_adj  = (const float*)d_in[6];
    const float* W_dis  = (const float*)d_in[7];
    const float* WC     = (const float*)d_in[8];
    const float* bWC    = (const float*)d_in[9];
    const float* bias   = (const float*)d_in[10];
    const int* uid      = (const int*)d_in[11];
    const int* adj      = (const int*)d_in[12];
    const int* dis      = (const int*)d_in[13];
    const int* nidx     = (const int*)d_in[14];
    float* out          = (float*)d_out;

    cudaFuncSetAttribute(gemm_hmma_kernel,
                         cudaFuncAttributeMaxDynamicSharedMemorySize, GSM_TOT);

    fold1_kernel<<<dim3(128, 2), 128>>>(W_adj, Wa_adj, ba_adj,
                                        W_dis, Wa_dis, ba_dis);
    fold2_kernel<<<384, 384>>>(WC, W_self, bWC, bias);
    gather_mean_kernel<<<U_NODES, 128>>>(emb, uid, adj, dis);
    gemm_hmma_kernel<<<dim3(3, 128), 256, GSM_TOT>>>();
    norm_gather_kernel<<<B_OUT / 8, 256>>>(nidx, out);
}

// round 9
// speedup vs baseline: 1.1853x; 1.1853x over previous
#include <cuda_runtime.h>
#include <cuda_bf16.h>
#include <cuda_fp16.h>
#include <cstdint>
#include <cstddef>

// ---------------------------------------------------------------------------
// SageLayer pipeline v8
//   out[b] = normalize(leaky( X @ A^T + c ))[nodes_idx]
//   X[u] = [ emb[uid[u]] | mean_k emb[adj[u,k]] | mean_k emb[dis[u,k]] ]
//   Weights folded to one 384x384 fp16 matrix (one-stage algebra per row:
//   WC2@(W@Wa) = (WC2@W)@Wa), folded INSIDE the gather grid (blocks 0..383)
//   so fold compute hides under the DRAM-bound gather.
//   Gather: warp-per-8-rows LDG.128 with smem cross-warp reduce.
//   GEMM: fp16 mma.sync, K=384, 3-stage cp.async (validated R5-R7).
// ---------------------------------------------------------------------------

#define U_NODES 16384
#define K_NEIGH 32
#define D_IN    128
#define D_OUT   384
#define B_OUT   32768
#define FOLD_BLOCKS 384

// ---- device scratch ----
__device__ __align__(16) float g_c[384];
__device__ __align__(16) __half g_X[(size_t)U_NODES * 384];
__device__ __align__(16) __half g_B[384 * 384];            // folded A[n][k]
__device__ __align__(16) float g_Y[(size_t)U_NODES * 384];

// ---- helpers ----
__device__ __forceinline__ uint32_t smem_u32(const void* p) {
    uint32_t a;
    asm("{ .reg .u64 t; cvta.to.shared.u64 t, %1; cvt.u32.u64 %0, t; }"
        : "=r"(a) : "l"(p));
    return a;
}
__device__ __forceinline__ void cp_async16(uint32_t dst, const void* src) {
    asm volatile("cp.async.cg.shared.global [%0], [%1], 16;"
                 :: "r"(dst), "l"(src) : "memory");
}
__device__ __forceinline__ void cp_commit() {
    asm volatile("cp.async.commit_group;" ::: "memory");
}
template <int N>
__device__ __forceinline__ void cp_wait() {
    asm volatile("cp.async.wait_group %0;" :: "n"(N) : "memory");
}
__device__ __forceinline__ void ldsm_x4(uint32_t& r0, uint32_t& r1,
                                        uint32_t& r2, uint32_t& r3, uint32_t a) {
    asm volatile("ldmatrix.sync.aligned.m8n8.x4.shared.b16 {%0,%1,%2,%3}, [%4];"
                 : "=r"(r0), "=r"(r1), "=r"(r2), "=r"(r3) : "r"(a));
}
__device__ __forceinline__ void mma16816(float& c0, float& c1, float& c2, float& c3,
                                         uint32_t a0, uint32_t a1, uint32_t a2, uint32_t a3,
                                         uint32_t b0, uint32_t b1) {
    asm volatile(
        "mma.sync.aligned.m16n8k16.row.col.f32.f16.f16.f32 "
        "{%0,%1,%2,%3}, {%4,%5,%6,%7}, {%8,%9}, {%0,%1,%2,%3};"
        : "+f"(c0), "+f"(c1), "+f"(c2), "+f"(c3)
        : "r"(a0), "r"(a1), "r"(a2), "r"(a3), "r"(b0), "r"(b1));
}
__device__ __forceinline__ uint32_t pack_half2_u32(float a, float b) {
    __half2 h = __floats2half2_rn(a, b);
    return *(uint32_t*)&h;
}

// ---------------------------------------------------------------------------
// fused fold + gather kernel
//   blocks [0, 384):        fold output-row n = blockIdx.x of B and c
//   blocks [384, 384+16384): gather+mean node u = blockIdx.x - 384
//   128 threads per block.
// ---------------------------------------------------------------------------
__global__ void __launch_bounds__(128) fold_gather_kernel(
        const float* __restrict__ emb,
        const int* __restrict__ uid,
        const int* __restrict__ adj,
        const int* __restrict__ dis,
        const float* __restrict__ Wa_adj,
        const float* __restrict__ ba_adj,
        const float* __restrict__ Wa_dis,
        const float* __restrict__ ba_dis,
        const float* __restrict__ W_self,
        const float* __restrict__ W_adj,
        const float* __restrict__ W_dis,
        const float* __restrict__ WC,
        const float* __restrict__ bWC,
        const float* __restrict__ bias) {
    const int t = threadIdx.x;

    if (blockIdx.x < FOLD_BLOCKS) {
        // ---------------- fold: B[n][:] (fp16) and c[n] ---------------------
        const int n = blockIdx.x;
        __shared__ float wcn[384];
        __shared__ float tbuf[128];
        __shared__ float red[128];

        wcn[t]       = WC[n * 384 + t];
        wcn[t + 128] = WC[n * 384 + 128 + t];
        wcn[t + 256] = WC[n * 384 + 256 + t];
        __syncthreads();

        // self segment: B[n][k] = sum_e wcn[e] * W_self[e][k],  k = t
        {
            float a = 0.f;
#pragma unroll 8
            for (int e = 0; e < 128; e++)
                a += wcn[e] * W_self[e * 128 + t];
            g_B[n * 384 + t] = __float2half_rn(a);
        }

        float csum = 0.f;

        // adj segment: tv[e] = sum_g wcn[128+g] * W_adj[g][e]
        //              B[n][128+k] = sum_e tv[e] * Wa_adj[e][k]
        //              c += sum_e tv[e] * ba_adj[e]
        {
            float tv = 0.f;
#pragma unroll 8
            for (int g = 0; g < 128; g++)
                tv += wcn[128 + g] * W_adj[g * 128 + t];
            tbuf[t] = tv;
            __syncthreads();
            float a2 = 0.f;
#pragma unroll 8
            for (int e = 0; e < 128; e++)
                a2 += tbuf[e] * Wa_adj[e * 128 + t];
            g_B[n * 384 + 128 + t] = __float2half_rn(a2);
            red[t] = tv * ba_adj[t];
            __syncthreads();
#pragma unroll
            for (int s = 64; s > 0; s >>= 1) {
                if (t < s) red[t] += red[t + s];
                __syncthreads();
            }
            csum += red[0];
            __syncthreads();
        }

        // dis segment
        {
            float tv = 0.f;
#pragma unroll 8
            for (int g = 0; g < 128; g++)
                tv += wcn[256 + g] * W_dis[g * 128 + t];
            tbuf[t] = tv;
            __syncthreads();
            float a2 = 0.f;
#pragma unroll 8
            for (int e = 0; e < 128; e++)
                a2 += tbuf[e] * Wa_dis[e * 128 + t];
            g_B[n * 384 + 256 + t] = __float2half_rn(a2);
            red[t] = tv * ba_dis[t];
            __syncthreads();
#pragma unroll
            for (int s = 64; s > 0; s >>= 1) {
                if (t < s) red[t] += red[t + s];
                __syncthreads();
            }
            csum += red[0];
        }

        if (t == 0) g_c[n] = csum + bWC[n] + bias[n];
        return;
    }

    // ---------------- gather + mean (float4 per lane) -----------------------
    const int u = blockIdx.x - FOLD_BLOCKS;
    const int lane = t & 31;
    const int w = t >> 5;

    __shared__ int sa[K_NEIGH];
    __shared__ int sd[K_NEIGH];
    __shared__ int sself;
    __shared__ float4 part[2][4][32];

    if (t < 32)       sa[t]      = adj[(size_t)u * K_NEIGH + t];
    else if (t < 64)  sd[t - 32] = dis[(size_t)u * K_NEIGH + (t - 32)];
    else if (t == 64) sself      = uid[u];
    __syncthreads();

    const float4* e4 = (const float4*)emb;   // 32 float4 per 128-dim row

    // warp 2 also loads the self row (issued early, independent)
    float4 vself;
    if (w == 2) vself = e4[(size_t)sself * 32 + lane];

    float4 aa = make_float4(0.f, 0.f, 0.f, 0.f);
    float4 ad = make_float4(0.f, 0.f, 0.f, 0.f);
#pragma unroll
    for (int j = 0; j < 8; j++) {
        const int k = w * 8 + j;
        float4 va = e4[(size_t)sa[k] * 32 + lane];
        float4 vd = e4[(size_t)sd[k] * 32 + lane];
        aa.x += va.x; aa.y += va.y; aa.z += va.z; aa.w += va.w;
        ad.x += vd.x; ad.y += vd.y; ad.z += vd.z; ad.w += vd.w;
    }
    part[0][w][lane] = aa;
    part[1][w][lane] = ad;

    // self store (dims lane*4..lane*4+3) — independent of the reduce
    if (w == 2) {
        uint2 pk;
        pk.x = pack_half2_u32(vself.x, vself.y);
        pk.y = pack_half2_u32(vself.z, vself.w);
        *(uint2*)&g_X[(size_t)u * 384 + lane * 4] = pk;
    }
    __syncthreads();

    // reduce tasks: t in [0,32): adj dims l*4.., t in [32,64): dis
    if (t < 64) {
        const int which = t >> 5;       // 0=adj, 1=dis
        const int l = t & 31;
        float4 s0 = part[which][0][l];
        float4 s1 = part[which][1][l];
        float4 s2 = part[which][2][l];
        float4 s3 = part[which][3][l];
        const float sc = 1.0f / 32.0f;
        float x0 = (s0.x + s1.x + s2.x + s3.x) * sc;
        float x1 = (s0.y + s1.y + s2.y + s3.y) * sc;
        float x2 = (s0.z + s1.z + s2.z + s3.z) * sc;
        float x3 = (s0.w + s1.w + s2.w + s3.w) * sc;
        uint2 pk;
        pk.x = pack_half2_u32(x0, x1);
        pk.y = pack_half2_u32(x2, x3);
        *(uint2*)&g_X[(size_t)u * 384 + 128 + which * 128 + l * 4] = pk;
    }
}

// ---------------------------------------------------------------------------
// GEMM: Y = leaky( X[16384,384] @ A^T + c ) via fp16 mma.sync
// K = 384, k-chunk 64, 6 iters. CTA 128x128, 8 warps (4m x 2n), warp 32x64.
// 3-stage cp.async pipeline, ONE __syncthreads per iter.
// smem rows padded to 144 B (stride 36 words -> conflict-free ldmatrix).
// ---------------------------------------------------------------------------
#define KCH      64
#define ROWB     144
#define STG_OP   (128 * ROWB)           // 18432 B per operand per stage
#define STG_B    (2 * STG_OP)           // 36864 B per stage (A+B)
#define NSTG     3
#define GSM_TOT  (NSTG * STG_B)         // 110592 B

__global__ __launch_bounds__(256, 2) void gemm_hmma_kernel() {
    extern __shared__ char gsm[];
    const uint32_t base = smem_u32(gsm);

    const int t = threadIdx.x;
    const int lane = t & 31;
    const int wid = t >> 5;
    const int wm = wid & 3;
    const int wn = wid >> 2;
    const int n0 = blockIdx.x * 128;
    const int m0 = blockIdx.y * 128;

    const uint32_t a_lm = (uint32_t)((lane & 15) * ROWB + (lane >> 4) * 16);
    const uint32_t b_lm = (uint32_t)(((lane & 7) + ((lane >> 4) << 3)) * ROWB
                                     + (((lane >> 3) & 1) << 4));

    float acc[2][8][4];
#pragma unroll
    for (int i = 0; i < 2; i++)
#pragma unroll
        for (int j = 0; j < 8; j++)
#pragma unroll
            for (int q = 0; q < 4; q++) acc[i][j][q] = 0.f;

    auto load_iter = [&](int it, int s) {
        const int kc = it * KCH;
        const uint32_t sb = base + (uint32_t)(s * STG_B);
#pragma unroll
        for (int j = 0; j < 4; j++) {
            const int q = t + j * 256;
            const int r = q >> 3;
            const int ch = q & 7;
            cp_async16(sb + (uint32_t)(r * ROWB + ch * 16),
                       g_X + (size_t)(m0 + r) * 384 + kc + ch * 8);
            cp_async16(sb + (uint32_t)(STG_OP + r * ROWB + ch * 16),
                       g_B + (size_t)(n0 + r) * 384 + kc + ch * 8);
        }
        cp_commit();
    };

    load_iter(0, 0);
    load_iter(1, 1);

    for (int it = 0; it < 6; it++) {
        if (it == 5) cp_wait<0>(); else cp_wait<1>();
        __syncthreads();

        const int s = it % NSTG;
        const uint32_t a_tile = base + (uint32_t)(s * STG_B + wm * 32 * ROWB) + a_lm;
        const uint32_t b_tile = base + (uint32_t)(s * STG_B + STG_OP + wn * 64 * ROWB) + b_lm;

#pragma unroll
        for (int ks = 0; ks < 4; ks++) {
            uint32_t af[2][4];
            uint32_t bf_[4][4];
#pragma unroll
            for (int mi = 0; mi < 2; mi++)
                ldsm_x4(af[mi][0], af[mi][1], af[mi][2], af[mi][3],
                        a_tile + (uint32_t)(mi * 16 * ROWB + ks * 32));
#pragma unroll
            for (int bj = 0; bj < 4; bj++)
                ldsm_x4(bf_[bj][0], bf_[bj][1], bf_[bj][2], bf_[bj][3],
                        b_tile + (uint32_t)(bj * 16 * ROWB + ks * 32));
#pragma unroll
            for (int mi = 0; mi < 2; mi++)
#pragma unroll
                for (int nj = 0; nj < 8; nj++)
                    mma16816(acc[mi][nj][0], acc[mi][nj][1],
                             acc[mi][nj][2], acc[mi][nj][3],
                             af[mi][0], af[mi][1], af[mi][2], af[mi][3],
                             bf_[nj >> 1][(nj & 1) * 2],
                             bf_[nj >> 1][(nj & 1) * 2 + 1]);
        }

        if (it + 2 < 6) load_iter(it + 2, (it + 2) % NSTG);
    }

    float cv[8][2];
#pragma unroll
    for (int nj = 0; nj < 8; nj++) {
        const int col = n0 + wn * 64 + nj * 8 + (lane & 3) * 2;
        cv[nj][0] = g_c[col];
        cv[nj][1] = g_c[col + 1];
    }
#pragma unroll
    for (int mi = 0; mi < 2; mi++) {
        const int row = m0 + wm * 32 + mi * 16 + (lane >> 2);
#pragma unroll
        for (int nj = 0; nj < 8; nj++) {
            const int col = n0 + wn * 64 + nj * 8 + (lane & 3) * 2;
            float y0 = acc[mi][nj][0] + cv[nj][0];
            float y1 = acc[mi][nj][1] + cv[nj][1];
            float y2 = acc[mi][nj][2] + cv[nj][0];
            float y3 = acc[mi][nj][3] + cv[nj][1];
            y0 = (y0 > 0.f) ? y0 : 0.2f * y0;
            y1 = (y1 > 0.f) ? y1 : 0.2f * y1;
            y2 = (y2 > 0.f) ? y2 : 0.2f * y2;
            y3 = (y3 > 0.f) ? y3 : 0.2f * y3;
            *(float2*)&g_Y[(size_t)row * 384 + col]       = make_float2(y0, y1);
            *(float2*)&g_Y[(size_t)(row + 8) * 384 + col] = make_float2(y2, y3);
        }
    }
}

// ---------------------------------------------------------------------------
// norm_gather: out[b] = normalize(Y[nodes_idx[b]])
// ---------------------------------------------------------------------------
__global__ void norm_gather_kernel(const int* __restrict__ nodes_idx,
                                   float* __restrict__ out) {
    __shared__ int sidx[8];
    const int w = threadIdx.x >> 5;
    const int l = threadIdx.x & 31;
    if (threadIdx.x < 8) sidx[threadIdx.x] = nodes_idx[blockIdx.x * 8 + threadIdx.x];
    __syncthreads();

    const int b = blockIdx.x * 8 + w;
    const int u = sidx[w];

    const float4* yr = (const float4*)(g_Y + (size_t)u * 384);
    float4 v0 = yr[l];
    float4 v1 = yr[l + 32];
    float4 v2 = yr[l + 64];

    float s = v0.x * v0.x + v0.y * v0.y + v0.z * v0.z + v0.w * v0.w
            + v1.x * v1.x + v1.y * v1.y + v1.z * v1.z + v1.w * v1.w
            + v2.x * v2.x + v2.y * v2.y + v2.z * v2.z + v2.w * v2.w;
#pragma unroll
    for (int off = 16; off > 0; off >>= 1)
        s += __shfl_xor_sync(0xffffffffu, s, off);

    const float inv = 1.0f / fmaxf(sqrtf(s), 1e-12f);

    float4* o = (float4*)(out + (size_t)b * 384);
    v0.x *= inv; v0.y *= inv; v0.z *= inv; v0.w *= inv;
    v1.x *= inv; v1.y *= inv; v1.z *= inv; v1.w *= inv;
    v2.x *= inv; v2.y *= inv; v2.z *= inv; v2.w *= inv;
    o[l]      = v0;
    o[l + 32] = v1;
    o[l + 64] = v2;
}

// ---------------------------------------------------------------------------
extern "C" void kernel_launch(void* const* d_in, const int* in_sizes, int n_in,
                              void* d_out, int out_size) {
    const float* emb    = (const float*)d_in[0];
    const float* Wa_adj = (const float*)d_in[1];
    const float* ba_adj = (const float*)d_in[2];
    const float* Wa_dis = (const float*)d_in[3];
    const float* ba_dis = (const float*)d_in[4];
    const float* W_self = (const float*)d_in[5];
    const float* W_adj  = (const float*)d_in[6];
    const float* W_dis  = (const float*)d_in[7];
    const float* WC     = (const float*)d_in[8];
    const float* bWC    = (const float*)d_in[9];
    const float* bias   = (const float*)d_in[10];
    const int* uid      = (const int*)d_in[11];
    const int* adj      = (const int*)d_in[12];
    const int* dis      = (const int*)d_in[13];
    const int* nidx     = (const int*)d_in[14];
    float* out          = (float*)d_out;

    cudaFuncSetAttribute(gemm_hmma_kernel,
                         cudaFuncAttributeMaxDynamicSharedMemorySize, GSM_TOT);

    fold_gather_kernel<<<FOLD_BLOCKS + U_NODES, 128>>>(
        emb, uid, adj, dis,
        Wa_adj, ba_adj, Wa_dis, ba_dis,
        W_self, W_adj, W_dis, WC, bWC, bias);
    gemm_hmma_kernel<<<dim3(3, 128), 256, GSM_TOT>>>();
    norm_gather_kernel<<<B_OUT / 8, 256>>>(nidx, out);
}